// round 8
// baseline (speedup 1.0000x reference)
#include <cuda_runtime.h>
#include <float.h>

// Problem constants
#define B_   16
#define P_   4096
#define T_   1024
#define G_   64                 // 64x64 cells of size 8.0 covering [0,512)
#define NC_  (G_*G_)
#define RADIUS_ 2.5f

#define NT_  1024               // 1 block per image; 32 warps
#define PPT_ (P_/NT_)           // 4 preds per thread

#define SCALE_ 17179869184.0    // 2^34 fixed-point scale (sums < 2^53, exact in int64)

// Global state: ONLY cross-block accumulators (reset by finalizer each launch).
__device__ unsigned long long g_acc_obj;
__device__ unsigned long long g_acc_cobj;
__device__ unsigned long long g_acc_creg;
__device__ unsigned int       g_done;     // monotonic; finalize when (t % B_) == B_-1

__global__ void __launch_bounds__(NT_, 1)
fused_kernel(const float* __restrict__ pred, const float* __restrict__ gt,
             float* __restrict__ out) {
    // Per-image smem state (launch-fresh: no cleanup/epoch machinery needed)
    __shared__ int                s_pack[NC_/2];      // 2 cells per int (16-bit halves): counts, then cursors
    __shared__ unsigned short     s_off [NC_ + 1];    // CSR starts (preserved)
    __shared__ float4             s_data[T_];         // CSR target data {cls,x,y,t_as_float}
    __shared__ unsigned long long s_best[T_];         // ~((dsq<<32)|p); 0 = empty
    __shared__ unsigned int       s_corr[P_/32];      // per-pred correctness bitmask
    __shared__ int                s_wsum[32];         // block scan
    __shared__ long long          s_red[3*32];        // final reduction

    const int tid  = threadIdx.x;
    const int lane = tid & 31;
    const int wrp  = tid >> 5;
    const int b    = blockIdx.x;
    const float4* __restrict__ pred4 = reinterpret_cast<const float4*>(pred) + b * P_;

    // ---- Phase A: zero smem + load my target + count -----------------------
    s_best[tid] = 0ull;
    if (tid < P_/32)   s_corr[tid] = 0u;
    s_pack[tid] = 0; s_pack[tid + NT_] = 0;           // NC_/2 == 2048

    const float* g = gt + ((size_t)b * T_ + tid) * 3;
    float tc = g[0], tx = g[1], ty = g[2];
    int tcx = (int)(tx * 0.125f); tcx = min(max(tcx, 0), G_-1);
    int tcy = (int)(ty * 0.125f); tcy = min(max(tcy, 0), G_-1);
    int tcell = tcy * G_ + tcx;
    __syncthreads();
    atomicAdd(&s_pack[tcell >> 1], 1 << ((tcell & 1) * 16));
    __syncthreads();

    // ---- Prefix scan: counts -> CSR starts (4 cells per thread) ------------
    int cnts[4];
    #pragma unroll
    for (int k = 0; k < 4; k++) {
        int c = tid * 4 + k;
        cnts[k] = (s_pack[c >> 1] >> ((c & 1) * 16)) & 0xFFFF;
    }
    int tot = cnts[0] + cnts[1] + cnts[2] + cnts[3];
    int incl = tot;
    #pragma unroll
    for (int o = 1; o < 32; o <<= 1) {
        int n = __shfl_up_sync(0xFFFFFFFFu, incl, o);
        if (lane >= o) incl += n;
    }
    if (lane == 31) s_wsum[wrp] = incl;
    __syncthreads();
    if (wrp == 0) {
        int v = s_wsum[lane];
        int wi = v;
        #pragma unroll
        for (int o = 1; o < 32; o <<= 1) {
            int n = __shfl_up_sync(0xFFFFFFFFu, wi, o);
            if (lane >= o) wi += n;
        }
        s_wsum[lane] = wi - v;                        // exclusive warp base
    }
    __syncthreads();
    int run = s_wsum[wrp] + (incl - tot);             // exclusive start for this thread
    #pragma unroll
    for (int k = 0; k < 4; k++) { s_off[tid*4 + k] = (unsigned short)run; run += cnts[k]; }
    if (tid == 0) s_off[NC_] = (unsigned short)T_;
    __syncthreads();

    // Rewrite s_pack as packed insert-cursors (= starts)
    #pragma unroll
    for (int q = 0; q < 2; q++) {
        int w2 = tid + q * NT_;
        s_pack[w2] = (int)s_off[2*w2] | ((int)s_off[2*w2 + 1] << 16);
    }
    __syncthreads();

    // ---- Insert my target into CSR -----------------------------------------
    {
        int sh  = (tcell & 1) * 16;
        int old = atomicAdd(&s_pack[tcell >> 1], 1 << sh);
        int slot = (old >> sh) & 0xFFFF;
        s_data[slot] = make_float4(tc, tx, ty, __int_as_float(tid));
    }
    __syncthreads();

    // ---- Phase B: 4 preds/thread, 2x2 cell scan (radius 2.5 < cell/2) ------
    float mind[PPT_], conf[PPT_];
    #pragma unroll
    for (int k = 0; k < PPT_; k++) {
        int p = tid + k * NT_;                        // coalesced
        float4 pr = __ldg(pred4 + p);                 // {cls,x,y,conf}
        conf[k] = pr.w;
        float cls = pr.x, x = pr.y, y = pr.z;

        int cx = (int)(x * 0.125f); cx = min(max(cx, 0), G_-1);
        int cy = (int)(y * 0.125f); cy = min(max(cy, 0), G_-1);
        float fx = x - (float)cx * 8.0f;
        float fy = y - (float)cy * 8.0f;
        int nx = cx + ((fx <= RADIUS_) ? -1 : ((fx >= 8.0f - RADIUS_) ? 1 : 0));
        int ny = cy + ((fy <= RADIUS_) ? -1 : ((fy >= 8.0f - RADIUS_) ? 1 : 0));
        bool vx = (nx != cx) & (nx >= 0) & (nx < G_);
        bool vy = (ny != cy) & (ny >= 0) & (ny < G_);

        int  cell[4]; bool ok[4];
        cell[0] = cy*G_ + cx;  ok[0] = true;
        cell[1] = cy*G_ + nx;  ok[1] = vx;
        cell[2] = ny*G_ + cx;  ok[2] = vy;
        cell[3] = ny*G_ + nx;  ok[3] = vx & vy;

        float md = FLT_MAX;
        #pragma unroll
        for (int q = 0; q < 4; q++) {
            if (!ok[q]) continue;
            int st = s_off[cell[q]], en = s_off[cell[q] + 1];
            for (int j = st; j < en; j++) {
                float4 v = s_data[j];
                float dx = x - v.y, dy = y - v.z;
                float dsq = dx*dx + dy*dy;
                md = fminf(md, dsq);
                float d = sqrtf(dsq + 1e-12f);
                if (d <= RADIUS_ && cls == v.x) {
                    int t = __float_as_int(v.w);
                    unsigned long long key =
                        ~(((unsigned long long)__float_as_uint(dsq) << 32) | (unsigned int)p);
                    atomicMax(&s_best[t], key);       // min (dsq, p) lexicographic
                }
            }
        }
        mind[k] = md;
    }
    __syncthreads();

    // ---- Phase C: per-target winner -> correctness bitmask -----------------
    {
        unsigned long long v = s_best[tid];
        if (v) {
            int p = (int)(~v & 0xFFFFFFFFull);
            atomicOr(&s_corr[p >> 5], 1u << (p & 31));
        }
    }
    __syncthreads();

    // ---- Phase D: per-pred losses (conf/mind still in registers) -----------
    long long accO = 0, accCO = 0, accCR = 0;
    #pragma unroll
    for (int k = 0; k < PPT_; k++) {
        int p = tid + k * NT_;
        float c = conf[k];
        float bce0 = fmaxf(c, 0.0f) + log1pf(expf(-fabsf(c)));   // BCE target 0
        accO += (long long)((double)bce0 * SCALE_);
        if ((s_corr[p >> 5] >> (p & 31)) & 1u) {
            float d = sqrtf(mind[k] + 1e-12f);
            float s = 1.0f / (1.0f + expf(-(RADIUS_ - d)));
            accCO += (long long)((double)c * SCALE_);
            accCR += (long long)((double)s * SCALE_);
        }
    }

    // ---- Block reduce (deterministic) + 3 global REDs + finalize -----------
    #pragma unroll
    for (int o = 16; o; o >>= 1) {
        accO  += __shfl_down_sync(0xFFFFFFFFu, accO,  o);
        accCO += __shfl_down_sync(0xFFFFFFFFu, accCO, o);
        accCR += __shfl_down_sync(0xFFFFFFFFu, accCR, o);
    }
    if (lane == 0) { s_red[wrp] = accO; s_red[32 + wrp] = accCO; s_red[64 + wrp] = accCR; }
    __syncthreads();
    if (tid == 0) {
        long long to = 0, tco = 0, tcr = 0;
        #pragma unroll
        for (int w = 0; w < 32; w++) { to += s_red[w]; tco += s_red[32+w]; tcr += s_red[64+w]; }
        atomicAdd(&g_acc_obj,  (unsigned long long)to);
        if (tco) atomicAdd(&g_acc_cobj, (unsigned long long)tco);
        if (tcr) atomicAdd(&g_acc_creg, (unsigned long long)tcr);
        __threadfence();
        unsigned int t = atomicAdd(&g_done, 1u);
        if ((t % (unsigned)B_) == (unsigned)(B_ - 1)) {            // last of 16 blocks
            long long o  = (long long)atomicAdd(&g_acc_obj,  0ull);
            long long co = (long long)atomicAdd(&g_acc_cobj, 0ull);
            long long cr = (long long)atomicAdd(&g_acc_creg, 0ull);
            double inv = 1.0 / (SCALE_ * 65536.0);
            out[0] = (float)(((double)o - (double)co) * inv);      // obj_loss
            out[1] = (float)(1.0 - (double)cr * inv);              // reg_loss
            atomicExch(&g_acc_obj,  0ull);                         // reset for next replay
            atomicExch(&g_acc_cobj, 0ull);
            atomicExch(&g_acc_creg, 0ull);
        }
    }
}

extern "C" void kernel_launch(void* const* d_in, const int* in_sizes, int n_in,
                              void* d_out, int out_size) {
    const float* pred = (const float*)d_in[0];
    const float* gt   = (const float*)d_in[1];
    if (n_in >= 2 && in_sizes[0] == B_*T_*3) {   // defensive input-order check
        const float* tmp = pred; pred = gt; gt = tmp;
    }
    (void)out_size;
    fused_kernel<<<B_, NT_>>>(pred, gt, (float*)d_out);
}

// round 9
// speedup vs baseline: 1.4735x; 1.4735x over previous
#include <cuda_runtime.h>
#include <float.h>

// Problem constants
#define B_   16
#define P_   4096
#define T_   1024
#define G_   64                 // 64x64 cells of size 8.0 covering [0,512)
#define NC_  (G_*G_)
#define RADIUS_ 2.5f

#define CSZ_  8                 // CTAs per cluster (per image)
#define NT_   512               // threads per CTA
#define NBTOT_ (B_*CSZ_)        // 128 blocks
#define PPC_  (P_/CSZ_)         // 512 preds per CTA (1 per thread)

#define SCALE_ 17179869184.0    // 2^34 fixed-point scale (sums < 2^53, exact in int64)

// Global state: ONLY cross-block accumulators (reset by finalizer each launch).
__device__ unsigned long long g_acc_obj;
__device__ unsigned long long g_acc_cobj;
__device__ unsigned long long g_acc_creg;
__device__ unsigned int       g_done;     // monotonic; finalize when (t % NBTOT_) == NBTOT_-1

__device__ __forceinline__ unsigned smem_u32(const void* p) {
    return (unsigned)__cvta_generic_to_shared(p);
}
__device__ __forceinline__ unsigned mapa_rank(unsigned addr, unsigned rank) {
    unsigned r;
    asm("mapa.shared::cluster.u32 %0, %1, %2;" : "=r"(r) : "r"(addr), "r"(rank));
    return r;
}
__device__ __forceinline__ unsigned ctarank() {
    unsigned r; asm("mov.u32 %0, %%cluster_ctarank;" : "=r"(r)); return r;
}
__device__ __forceinline__ void cluster_sync() {
    asm volatile("barrier.cluster.arrive.aligned;" ::: "memory");
    asm volatile("barrier.cluster.wait.aligned;"   ::: "memory");
}
__device__ __forceinline__ void red_max_u64_cluster(unsigned addr, unsigned long long v) {
    asm volatile("red.relaxed.cluster.shared::cluster.max.u64 [%0], %1;"
                 :: "r"(addr), "l"(v) : "memory");
}
__device__ __forceinline__ void red_or_b32_cluster(unsigned addr, unsigned v) {
    asm volatile("red.relaxed.cluster.shared::cluster.or.b32 [%0], %1;"
                 :: "r"(addr), "r"(v) : "memory");
}

__global__ void __launch_bounds__(NT_, 1) __cluster_dims__(CSZ_, 1, 1)
fused_kernel(const float* __restrict__ pred, const float* __restrict__ gt,
             float* __restrict__ out) {
    // Per-CTA smem (hash replicated per CTA; s_best used only on rank 0)
    __shared__ int                s_pack[NC_/2];    // 2 cells/int (16-bit): counts, then cursors
    __shared__ unsigned short     s_off [NC_ + 2];  // CSR starts
    __shared__ float4             s_data[T_];       // CSR targets {cls,x,y,t_as_float}
    __shared__ unsigned long long s_best[T_];       // rank0 only: ~((dsq<<32)|p); 0=empty
    __shared__ unsigned int       s_corr[PPC_/32];  // correctness bits for THIS CTA's 512 preds
    __shared__ int                s_wsum[16];
    __shared__ long long          s_red[3*16];

    const int tid  = threadIdx.x;
    const int lane = tid & 31;
    const int wrp  = tid >> 5;
    const unsigned rank = ctarank();
    const int b    = blockIdx.x / CSZ_;             // image
    const float4* __restrict__ pred4 = reinterpret_cast<const float4*>(pred) + b * P_;

    // ---- Phase A: zero smem, load+count targets (2 per thread) -------------
    #pragma unroll
    for (int q = 0; q < 4; q++) s_pack[tid + q*NT_] = 0;   // 2048 ints
    s_best[tid] = 0ull; s_best[tid + NT_] = 0ull;
    if (tid < PPC_/32) s_corr[tid] = 0u;

    float tcls[2], txr[2], tyr[2]; int tcell[2];
    #pragma unroll
    for (int k = 0; k < 2; k++) {
        int t = tid + k*NT_;
        const float* g = gt + ((size_t)b * T_ + t) * 3;
        tcls[k] = g[0]; txr[k] = g[1]; tyr[k] = g[2];
        int cx = (int)(txr[k] * 0.125f); cx = min(max(cx, 0), G_-1);
        int cy = (int)(tyr[k] * 0.125f); cy = min(max(cy, 0), G_-1);
        tcell[k] = cy*G_ + cx;
    }
    __syncthreads();
    #pragma unroll
    for (int k = 0; k < 2; k++)
        atomicAdd(&s_pack[tcell[k] >> 1], 1 << ((tcell[k] & 1) * 16));
    __syncthreads();

    // ---- Prefix scan: 8 cells per thread -> CSR starts ---------------------
    int cnts[8];
    #pragma unroll
    for (int k = 0; k < 8; k++) {
        int c = tid*8 + k;
        cnts[k] = (s_pack[c >> 1] >> ((c & 1) * 16)) & 0xFFFF;
    }
    int tot = 0;
    #pragma unroll
    for (int k = 0; k < 8; k++) tot += cnts[k];
    int incl = tot;
    #pragma unroll
    for (int o = 1; o < 32; o <<= 1) {
        int n = __shfl_up_sync(0xFFFFFFFFu, incl, o);
        if (lane >= o) incl += n;
    }
    if (lane == 31) s_wsum[wrp] = incl;
    __syncthreads();
    if (wrp == 0) {
        int v = (lane < 16) ? s_wsum[lane] : 0;
        int wi = v;
        #pragma unroll
        for (int o = 1; o < 32; o <<= 1) {
            int n = __shfl_up_sync(0xFFFFFFFFu, wi, o);
            if (lane >= o) wi += n;
        }
        if (lane < 16) s_wsum[lane] = wi - v;       // exclusive warp base
    }
    __syncthreads();
    int run = s_wsum[wrp] + (incl - tot);
    #pragma unroll
    for (int k = 0; k < 8; k++) { s_off[tid*8 + k] = (unsigned short)run; run += cnts[k]; }
    if (tid == 0) s_off[NC_] = (unsigned short)T_;
    __syncthreads();

    // Rewrite s_pack as packed insert cursors (= starts)
    #pragma unroll
    for (int q = 0; q < 4; q++) {
        int w2 = tid + q*NT_;
        s_pack[w2] = (int)s_off[2*w2] | ((int)s_off[2*w2 + 1] << 16);
    }
    __syncthreads();

    // ---- Insert targets into CSR -------------------------------------------
    #pragma unroll
    for (int k = 0; k < 2; k++) {
        int sh  = (tcell[k] & 1) * 16;
        int old = atomicAdd(&s_pack[tcell[k] >> 1], 1 << sh);
        int slot = (old >> sh) & 0xFFFF;
        s_data[slot] = make_float4(tcls[k], txr[k], tyr[k], __int_as_float(tid + k*NT_));
    }

    // Rank0's s_best zero + local hash must be ready before remote reds.
    cluster_sync();

    // ---- Phase B: 1 pred/thread, 2x2 cell scan (radius 2.5 < cell/2=4) -----
    const unsigned bestBase0 = mapa_rank(smem_u32(s_best), 0);  // rank0's s_best
    const int pg = (int)rank * PPC_ + tid;          // global pred id in image
    float4 pr = __ldg(pred4 + pg);                  // {cls,x,y,conf}
    const float conf = pr.w;
    float mind = FLT_MAX;
    {
        float cls = pr.x, x = pr.y, y = pr.z;
        int cx = (int)(x * 0.125f); cx = min(max(cx, 0), G_-1);
        int cy = (int)(y * 0.125f); cy = min(max(cy, 0), G_-1);
        float fx = x - (float)cx * 8.0f;
        float fy = y - (float)cy * 8.0f;
        int nx = cx + ((fx <= RADIUS_) ? -1 : ((fx >= 8.0f - RADIUS_) ? 1 : 0));
        int ny = cy + ((fy <= RADIUS_) ? -1 : ((fy >= 8.0f - RADIUS_) ? 1 : 0));
        bool vx = (nx != cx) & (nx >= 0) & (nx < G_);
        bool vy = (ny != cy) & (ny >= 0) & (ny < G_);

        int cell[4]; bool ok[4];
        cell[0] = cy*G_ + cx;  ok[0] = true;
        cell[1] = cy*G_ + nx;  ok[1] = vx;
        cell[2] = ny*G_ + cx;  ok[2] = vy;
        cell[3] = ny*G_ + nx;  ok[3] = vx & vy;

        #pragma unroll
        for (int q = 0; q < 4; q++) {
            if (!ok[q]) continue;
            int st = s_off[cell[q]], en = s_off[cell[q] + 1];
            for (int j = st; j < en; j++) {
                float4 v = s_data[j];
                float dx = x - v.y, dy = y - v.z;
                float dsq = dx*dx + dy*dy;
                mind = fminf(mind, dsq);
                float d = sqrtf(dsq + 1e-12f);
                if (d <= RADIUS_ && cls == v.x) {
                    int t = __float_as_int(v.w);
                    unsigned long long key =
                        ~(((unsigned long long)__float_as_uint(dsq) << 32) | (unsigned)pg);
                    red_max_u64_cluster(bestBase0 + t*8, key);   // min (dsq, p) lexicographic
                }
            }
        }
    }

    cluster_sync();   // all reds visible to rank 0

    // ---- Phase C: rank0 computes winners -> red.or to owner CTA's s_corr ---
    if (rank == 0) {
        const unsigned corrBaseLocal = smem_u32(s_corr);
        #pragma unroll
        for (int k = 0; k < 2; k++) {
            unsigned long long v = s_best[tid + k*NT_];
            if (v) {
                int p = (int)(~v & 0xFFFFFFFFull);   // global pred id
                unsigned owner = (unsigned)(p >> 9); // p / 512
                int pl = p & (PPC_ - 1);
                unsigned addr = mapa_rank(corrBaseLocal + (pl >> 5) * 4, owner);
                red_or_b32_cluster(addr, 1u << (pl & 31));
            }
        }
    }

    cluster_sync();   // correctness bits visible to owners

    // ---- Phase D: per-pred losses (conf/mind in registers) ------------------
    long long accO = 0, accCO = 0, accCR = 0;
    {
        float c = conf;
        float bce0 = fmaxf(c, 0.0f) + log1pf(expf(-fabsf(c)));   // BCE target 0
        accO = (long long)((double)bce0 * SCALE_);
        if ((s_corr[tid >> 5] >> (tid & 31)) & 1u) {
            float d = sqrtf(mind + 1e-12f);
            float s = 1.0f / (1.0f + expf(-(RADIUS_ - d)));
            accCO = (long long)((double)c * SCALE_);
            accCR = (long long)((double)s * SCALE_);
        }
    }
    #pragma unroll
    for (int o = 16; o; o >>= 1) {
        accO  += __shfl_down_sync(0xFFFFFFFFu, accO,  o);
        accCO += __shfl_down_sync(0xFFFFFFFFu, accCO, o);
        accCR += __shfl_down_sync(0xFFFFFFFFu, accCR, o);
    }
    if (lane == 0) { s_red[wrp] = accO; s_red[16 + wrp] = accCO; s_red[32 + wrp] = accCR; }
    __syncthreads();
    if (tid == 0) {
        long long to = 0, tco = 0, tcr = 0;
        #pragma unroll
        for (int w = 0; w < 16; w++) { to += s_red[w]; tco += s_red[16+w]; tcr += s_red[32+w]; }
        if (to)  atomicAdd(&g_acc_obj,  (unsigned long long)to);
        if (tco) atomicAdd(&g_acc_cobj, (unsigned long long)tco);
        if (tcr) atomicAdd(&g_acc_creg, (unsigned long long)tcr);
        __threadfence();
        unsigned int t = atomicAdd(&g_done, 1u);
        if ((t % (unsigned)NBTOT_) == (unsigned)(NBTOT_ - 1)) {   // last of 128 blocks
            long long o  = (long long)atomicAdd(&g_acc_obj,  0ull);
            long long co = (long long)atomicAdd(&g_acc_cobj, 0ull);
            long long cr = (long long)atomicAdd(&g_acc_creg, 0ull);
            double inv = 1.0 / (SCALE_ * 65536.0);
            out[0] = (float)(((double)o - (double)co) * inv);     // obj_loss
            out[1] = (float)(1.0 - (double)cr * inv);             // reg_loss
            atomicExch(&g_acc_obj,  0ull);                        // reset for next replay
            atomicExch(&g_acc_cobj, 0ull);
            atomicExch(&g_acc_creg, 0ull);
        }
    }
}

extern "C" void kernel_launch(void* const* d_in, const int* in_sizes, int n_in,
                              void* d_out, int out_size) {
    const float* pred = (const float*)d_in[0];
    const float* gt   = (const float*)d_in[1];
    if (n_in >= 2 && in_sizes[0] == B_*T_*3) {   // defensive input-order check
        const float* tmp = pred; pred = gt; gt = tmp;
    }
    (void)out_size;
    fused_kernel<<<NBTOT_, NT_>>>(pred, gt, (float*)d_out);
}